// round 6
// baseline (speedup 1.0000x reference)
#include <cuda_runtime.h>

#define T_TOK   8192
#define DMODEL  1024
#define NEXP    8
#define DFF     4096
#define CAP     1280   // int(1.25 * 8192 / 8)
#define BK      16

typedef unsigned int u32;
typedef unsigned long long ull;

// ---------------- scratch (device globals; no allocation) ----------------
__device__ float g_disp[(size_t)NEXP * CAP * DMODEL];   // 40 MB
__device__ float g_h   [(size_t)NEXP * CAP * DFF];      // 167 MB
__device__ float g_eo  [(size_t)NEXP * CAP * DMODEL];   // 40 MB
__device__ int   g_idx [T_TOK];
__device__ float g_gate[T_TOK];
__device__ int   g_slot[T_TOK];
__device__ int   g_cnt [NEXP];

// ---------------- packed f32x2 + async-copy helpers ----------------
__device__ __forceinline__ ull pk(float x, float y) {
    ull r; asm("mov.b64 %0, {%1, %2};" : "=l"(r) : "f"(x), "f"(y)); return r;
}
__device__ __forceinline__ void upk(ull v, float& x, float& y) {
    asm("mov.b64 {%0, %1}, %2;" : "=f"(x), "=f"(y) : "l"(v));
}
__device__ __forceinline__ ull ffma2(ull a, ull b, ull c) {
    ull d; asm("fma.rn.f32x2 %0, %1, %2, %3;" : "=l"(d) : "l"(a), "l"(b), "l"(c)); return d;
}
__device__ __forceinline__ u32 smem_u32(const void* p) {
    u32 a; asm("{ .reg .u64 t; cvta.to.shared.u64 t, %1; cvt.u32.u64 %0, t; }" : "=r"(a) : "l"(p));
    return a;
}
__device__ __forceinline__ void cpa16(u32 s, const void* g) {
    asm volatile("cp.async.cg.shared.global [%0], [%1], 16;" :: "r"(s), "l"(g));
}
__device__ __forceinline__ void cpa_commit() { asm volatile("cp.async.commit_group;" ::: "memory"); }
__device__ __forceinline__ void cpa_wait1()  { asm volatile("cp.async.wait_group 1;" ::: "memory"); }
__device__ __forceinline__ void cpa_wait0()  { asm volatile("cp.async.wait_group 0;" ::: "memory"); }

// ---------------- 1. gating ----------------
__global__ void gate_kernel(const float* __restrict__ x, const float* __restrict__ wg) {
    __shared__ float wgT[NEXP][DMODEL];
    int tid = threadIdx.x;
    for (int i = tid; i < DMODEL * NEXP; i += 256)
        wgT[i & 7][i >> 3] = wg[i];
    __syncthreads();
    int warp = tid >> 5, lane = tid & 31;
    int t = blockIdx.x * 8 + warp;
    const float* xr = x + (size_t)t * DMODEL;
    float acc[NEXP];
#pragma unroll
    for (int e = 0; e < NEXP; e++) acc[e] = 0.0f;
    for (int m = lane; m < DMODEL; m += 32) {
        float xv = xr[m];
#pragma unroll
        for (int e = 0; e < NEXP; e++) acc[e] += xv * wgT[e][m];
    }
#pragma unroll
    for (int e = 0; e < NEXP; e++)
#pragma unroll
        for (int o = 16; o; o >>= 1)
            acc[e] += __shfl_xor_sync(0xffffffffu, acc[e], o);
    if (lane == 0) {
        float mx = acc[0]; int a = 0;
#pragma unroll
        for (int e = 1; e < NEXP; e++)
            if (acc[e] > mx) { mx = acc[e]; a = e; }   // first-max, matches jnp.argmax
        float s = 0.0f;
#pragma unroll
        for (int e = 0; e < NEXP; e++) s += expf(acc[e] - mx);
        g_idx[t]  = a;
        g_gate[t] = 1.0f / s;
    }
}

// ---------------- 2. queue positions + per-expert counts ----------------
__global__ void scan_kernel() {
    __shared__ int wsum[8][NEXP];
    __shared__ int wbase[8][NEXP];
    int tid = threadIdx.x, wid = tid >> 5, lane = tid & 31;
    int loc[32];
    const int4* gp = (const int4*)(g_idx + tid * 32);
#pragma unroll
    for (int v = 0; v < 8; v++) {
        int4 q = gp[v];
        loc[v * 4 + 0] = q.x; loc[v * 4 + 1] = q.y;
        loc[v * 4 + 2] = q.z; loc[v * 4 + 3] = q.w;
    }
    int cnt[NEXP];
#pragma unroll
    for (int e = 0; e < NEXP; e++) cnt[e] = 0;
#pragma unroll
    for (int j = 0; j < 32; j++) cnt[loc[j]]++;
    int excl[NEXP];
#pragma unroll
    for (int e = 0; e < NEXP; e++) {
        int inc = cnt[e];
#pragma unroll
        for (int off = 1; off < 32; off <<= 1) {
            int n = __shfl_up_sync(0xffffffffu, inc, off);
            if (lane >= off) inc += n;
        }
        excl[e] = inc - cnt[e];
        if (lane == 31) wsum[wid][e] = inc;
    }
    __syncthreads();
    if (tid == 0) {
#pragma unroll
        for (int e = 0; e < NEXP; e++) {
            int run = 0;
            for (int w = 0; w < 8; w++) { wbase[w][e] = run; run += wsum[w][e]; }
            g_cnt[e] = (run < CAP) ? run : CAP;
        }
    }
    __syncthreads();
    int pos[NEXP];
#pragma unroll
    for (int e = 0; e < NEXP; e++) pos[e] = wbase[wid][e] + excl[e];
#pragma unroll
    for (int j = 0; j < 32; j++) {
        int e = loc[j];
        int p = pos[e]++;
        g_slot[tid * 32 + j] = (p < CAP) ? p : -1;
    }
}

// ---------------- 3. dispatch (gather tokens into [E,C,M]) ----------------
__global__ void gather_kernel(const float* __restrict__ x) {
    int t = blockIdx.x;
    int sl = g_slot[t];
    if (sl < 0) return;
    int e = g_idx[t];
    const float4* src = (const float4*)(x + (size_t)t * DMODEL);
    float4* dst = (float4*)(g_disp + ((size_t)e * CAP + sl) * DMODEL);
    dst[threadIdx.x] = src[threadIdx.x];
}

// ---------------- 4. per-expert SGEMM, zero-MOV f32x2 inner loop ----------------
// MT x 128 tile, BK=16, 256 threads, MR x 8 microtile.
// A held in regs, stored DUPLICATED into SMEM as (a,a) ull pairs -> direct ull2 frag loads.
// B via cp.async (triple-buffered), frags read as ulonglong2 (no packing MOVs).
template<int N, int K, bool RELU, int PHASE, int MT, int MR, int OCC>
__global__ __launch_bounds__(256, OCC)
void sgemm_kernel(const float* __restrict__ Bw, const float* __restrict__ biasb) {
    __shared__ __align__(16) ull  Aull[BK][MT + 2];
    __shared__ __align__(16) float Bs[3][BK][132];

    const int e = blockIdx.z;
    const int bm = blockIdx.y * MT;
    if (bm >= g_cnt[e]) return;          // expert under-filled: skip garbage rows

    const float* A;
    float* Cc;
    if (PHASE == 1) {
        A  = g_disp + (size_t)e * CAP * DMODEL;
        Cc = g_h    + (size_t)e * CAP * DFF;
    } else {
        A  = g_h    + (size_t)e * CAP * DFF;
        Cc = g_eo   + (size_t)e * CAP * DMODEL;
    }
    const float* B    = Bw    + (size_t)e * K * N;
    const float* bias = biasb + (size_t)e * N;

    const int bn = blockIdx.x * 128;
    const int tid = threadIdx.x;
    const int ty = tid >> 4, tx = tid & 15;
    constexpr int NCH = K / BK;
    constexpr int APT = MT / 16;         // A floats per thread per chunk (8 or 4)

    const int ar  = (APT == 8) ? (tid >> 1) : (tid >> 2);
    const int ak0 = (APT == 8) ? (tid & 1) * 8 : (tid & 3) * 4;
    const float* Aptr = A + (size_t)(bm + ar) * K + ak0;

    const int bk0  = tid >> 4;
    const int bseg = (tid * 2) & 31;
    const float* Bptr = B + (size_t)bk0 * N + bn + bseg * 4;
    u32 bs_st[3] = { smem_u32(&Bs[0][bk0][bseg * 4]),
                     smem_u32(&Bs[1][bk0][bseg * 4]),
                     smem_u32(&Bs[2][bk0][bseg * 4]) };

    float areg[2][APT];
#pragma unroll
    for (int q = 0; q < APT / 4; q++) {
        *(float4*)&areg[0][q * 4] = *(const float4*)(Aptr + q * 4);
        *(float4*)&areg[1][q * 4] = *(const float4*)(Aptr + BK + q * 4);
    }
    cpa16(bs_st[0],      Bptr);
    cpa16(bs_st[0] + 16, Bptr + 4);
    cpa_commit();
    cpa16(bs_st[1],      Bptr + (size_t)BK * N);
    cpa16(bs_st[1] + 16, Bptr + (size_t)BK * N + 4);
    cpa_commit();

    ull acc[MR][4];
#pragma unroll
    for (int i = 0; i < MR; i++)
#pragma unroll
        for (int j = 0; j < 4; j++) acc[i][j] = 0ull;

#pragma unroll 1
    for (int c = 0; c < NCH; c++) {
        if (c + 1 < NCH) cpa_wait1(); else cpa_wait0();
        __syncthreads();                            // all warps done with Aull(c-1) & Bs[(c-1)%3]
        // store chunk c's A fragment, duplicated, transposed
#pragma unroll
        for (int j = 0; j < APT; j++) {
            float v = areg[c & 1][j];
            Aull[ak0 + j][ar] = pk(v, v);
        }
        __syncthreads();                            // Aull(c) visible
        if (c + 2 < NCH) {
            const float* ap2 = Aptr + (size_t)(c + 2) * BK;
#pragma unroll
            for (int q = 0; q < APT / 4; q++)
                *(float4*)&areg[c & 1][q * 4] = *(const float4*)(ap2 + q * 4);
            const float* bp2g = Bptr + (size_t)(c + 2) * BK * N;
            u32 bss = bs_st[(c + 2) % 3];
            cpa16(bss,      bp2g);
            cpa16(bss + 16, bp2g + 4);
            cpa_commit();
        }
        const int s = c % 3;
#pragma unroll
        for (int kk = 0; kk < BK; kk++) {
            const ull* arow = &Aull[kk][ty * MR];
            ulonglong2 A0 = *(const ulonglong2*)(arow);
            ulonglong2 A1 = *(const ulonglong2*)(arow + 2);
            const float* brow = &Bs[s][kk][tx * 8];
            ulonglong2 B0 = *(const ulonglong2*)(brow);
            ulonglong2 B1 = *(const ulonglong2*)(brow + 4);
            ull bp0 = B0.x, bp1 = B0.y, bp2 = B1.x, bp3 = B1.y;
            ull ap[MR];
            ap[0] = A0.x; ap[1] = A0.y; ap[2] = A1.x; ap[3] = A1.y;
            if (MR == 8) {
                ulonglong2 A2 = *(const ulonglong2*)(arow + 4);
                ulonglong2 A3 = *(const ulonglong2*)(arow + 6);
                ap[4] = A2.x; ap[5] = A2.y; ap[6] = A3.x; ap[7] = A3.y;
            }
#pragma unroll
            for (int i = 0; i < MR; i++) {
                acc[i][0] = ffma2(ap[i], bp0, acc[i][0]);
                acc[i][1] = ffma2(ap[i], bp1, acc[i][1]);
                acc[i][2] = ffma2(ap[i], bp2, acc[i][2]);
                acc[i][3] = ffma2(ap[i], bp3, acc[i][3]);
            }
        }
    }

    // epilogue: bias (+relu) + store
    float bvals[8];
#pragma unroll
    for (int j = 0; j < 8; j++) bvals[j] = bias[bn + tx * 8 + j];
#pragma unroll
    for (int i = 0; i < MR; i++) {
        float o[8];
        upk(acc[i][0], o[0], o[1]);
        upk(acc[i][1], o[2], o[3]);
        upk(acc[i][2], o[4], o[5]);
        upk(acc[i][3], o[6], o[7]);
#pragma unroll
        for (int j = 0; j < 8; j++) {
            float v = o[j] + bvals[j];
            if (RELU) v = fmaxf(v, 0.0f);
            o[j] = v;
        }
        float* crow = Cc + (size_t)(bm + ty * MR + i) * N + bn + tx * 8;
        *(float4*)crow       = make_float4(o[0], o[1], o[2], o[3]);
        *(float4*)(crow + 4) = make_float4(o[4], o[5], o[6], o[7]);
    }
}

// ---------------- 5. combine ----------------
__global__ void combine_kernel(float* __restrict__ out) {
    int t = blockIdx.x;
    int sl = g_slot[t];
    float4* o = (float4*)(out + (size_t)t * DMODEL);
    int i = threadIdx.x;
    if (sl < 0) {
        o[i] = make_float4(0.f, 0.f, 0.f, 0.f);
        return;
    }
    float g = g_gate[t];
    int e = g_idx[t];
    float4 v = ((const float4*)(g_eo + ((size_t)e * CAP + sl) * DMODEL))[i];
    o[i] = make_float4(v.x * g, v.y * g, v.z * g, v.w * g);
}

// ---------------- launch ----------------
extern "C" void kernel_launch(void* const* d_in, const int* in_sizes, int n_in,
                              void* d_out, int out_size) {
    const float* x  = (const float*)d_in[0];   // [4,2048,1024]
    const float* wg = (const float*)d_in[1];   // [1024,8]
    const float* w1 = (const float*)d_in[2];   // [8,1024,4096]
    const float* b1 = (const float*)d_in[3];   // [8,4096]
    const float* w2 = (const float*)d_in[4];   // [8,4096,1024]
    const float* b2 = (const float*)d_in[5];   // [8,1024]
    float* out = (float*)d_out;                // [4,2048,1024]

    gate_kernel<<<T_TOK / 8, 256>>>(x, wg);
    scan_kernel<<<1, 256>>>();
    gather_kernel<<<T_TOK, 256>>>(x);
    // GEMM1: 128x128 tiles, 8x8 microtile, occ 2
    sgemm_kernel<DFF, DMODEL, true, 1, 128, 8, 2>
        <<<dim3(DFF / 128, CAP / 128, NEXP), 256>>>(w1, b1);
    // GEMM2: 64x128 tiles, 4x8 microtile, occ 3 (wave-quantization fix)
    sgemm_kernel<DMODEL, DFF, false, 2, 64, 4, 3>
        <<<dim3(DMODEL / 128, CAP / 64, NEXP), 256>>>(w2, b2);
    combine_kernel<<<T_TOK, 256>>>(out);
}

// round 7
// speedup vs baseline: 1.4136x; 1.4136x over previous
#include <cuda_runtime.h>

#define T_TOK   8192
#define DMODEL  1024
#define NEXP    8
#define DFF     4096
#define CAP     1280   // int(1.25 * 8192 / 8)
#define BK      16
#define PADW    132
#define SPLITK  4

typedef unsigned int u32;
typedef unsigned long long ull;

// ---------------- scratch (device globals; no allocation) ----------------
__device__ float g_disp[(size_t)NEXP * CAP * DMODEL];              // 40 MB
__device__ float g_h   [(size_t)NEXP * CAP * DFF];                 // 167 MB
__device__ float g_part[(size_t)SPLITK * NEXP * CAP * DMODEL];     // 160 MB
__device__ int   g_idx [T_TOK];
__device__ float g_gate[T_TOK];
__device__ int   g_slot[T_TOK];
__device__ int   g_cnt [NEXP];

// ---------------- packed f32x2 + async-copy helpers ----------------
__device__ __forceinline__ ull pk(float x, float y) {
    ull r; asm("mov.b64 %0, {%1, %2};" : "=l"(r) : "f"(x), "f"(y)); return r;
}
__device__ __forceinline__ void upk(ull v, float& x, float& y) {
    asm("mov.b64 {%0, %1}, %2;" : "=f"(x), "=f"(y) : "l"(v));
}
__device__ __forceinline__ ull ffma2(ull a, ull b, ull c) {
    ull d; asm("fma.rn.f32x2 %0, %1, %2, %3;" : "=l"(d) : "l"(a), "l"(b), "l"(c)); return d;
}
__device__ __forceinline__ u32 smem_u32(const void* p) {
    u32 a; asm("{ .reg .u64 t; cvta.to.shared.u64 t, %1; cvt.u32.u64 %0, t; }" : "=r"(a) : "l"(p));
    return a;
}
__device__ __forceinline__ void cpa16(u32 s, const void* g) {
    asm volatile("cp.async.cg.shared.global [%0], [%1], 16;" :: "r"(s), "l"(g));
}
__device__ __forceinline__ void cpa_commit() { asm volatile("cp.async.commit_group;" ::: "memory"); }
__device__ __forceinline__ void cpa_wait1()  { asm volatile("cp.async.wait_group 1;" ::: "memory"); }
__device__ __forceinline__ void cpa_wait0()  { asm volatile("cp.async.wait_group 0;" ::: "memory"); }

// ---------------- 1. gating ----------------
__global__ void gate_kernel(const float* __restrict__ x, const float* __restrict__ wg) {
    __shared__ float wgT[NEXP][DMODEL];
    int tid = threadIdx.x;
    for (int i = tid; i < DMODEL * NEXP; i += 256)
        wgT[i & 7][i >> 3] = wg[i];
    __syncthreads();
    int warp = tid >> 5, lane = tid & 31;
    int t = blockIdx.x * 8 + warp;
    const float* xr = x + (size_t)t * DMODEL;
    float acc[NEXP];
#pragma unroll
    for (int e = 0; e < NEXP; e++) acc[e] = 0.0f;
    for (int m = lane; m < DMODEL; m += 32) {
        float xv = xr[m];
#pragma unroll
        for (int e = 0; e < NEXP; e++) acc[e] += xv * wgT[e][m];
    }
#pragma unroll
    for (int e = 0; e < NEXP; e++)
#pragma unroll
        for (int o = 16; o; o >>= 1)
            acc[e] += __shfl_xor_sync(0xffffffffu, acc[e], o);
    if (lane == 0) {
        float mx = acc[0]; int a = 0;
#pragma unroll
        for (int e = 1; e < NEXP; e++)
            if (acc[e] > mx) { mx = acc[e]; a = e; }   // first-max, matches jnp.argmax
        float s = 0.0f;
#pragma unroll
        for (int e = 0; e < NEXP; e++) s += expf(acc[e] - mx);
        g_idx[t]  = a;
        g_gate[t] = 1.0f / s;
    }
}

// ---------------- 2. queue positions + per-expert counts ----------------
__global__ void scan_kernel() {
    __shared__ int wsum[8][NEXP];
    __shared__ int wbase[8][NEXP];
    int tid = threadIdx.x, wid = tid >> 5, lane = tid & 31;
    int loc[32];
    const int4* gp = (const int4*)(g_idx + tid * 32);
#pragma unroll
    for (int v = 0; v < 8; v++) {
        int4 q = gp[v];
        loc[v * 4 + 0] = q.x; loc[v * 4 + 1] = q.y;
        loc[v * 4 + 2] = q.z; loc[v * 4 + 3] = q.w;
    }
    int cnt[NEXP];
#pragma unroll
    for (int e = 0; e < NEXP; e++) cnt[e] = 0;
#pragma unroll
    for (int j = 0; j < 32; j++) cnt[loc[j]]++;
    int excl[NEXP];
#pragma unroll
    for (int e = 0; e < NEXP; e++) {
        int inc = cnt[e];
#pragma unroll
        for (int off = 1; off < 32; off <<= 1) {
            int n = __shfl_up_sync(0xffffffffu, inc, off);
            if (lane >= off) inc += n;
        }
        excl[e] = inc - cnt[e];
        if (lane == 31) wsum[wid][e] = inc;
    }
    __syncthreads();
    if (tid == 0) {
#pragma unroll
        for (int e = 0; e < NEXP; e++) {
            int run = 0;
            for (int w = 0; w < 8; w++) { wbase[w][e] = run; run += wsum[w][e]; }
            g_cnt[e] = (run < CAP) ? run : CAP;
        }
    }
    __syncthreads();
    int pos[NEXP];
#pragma unroll
    for (int e = 0; e < NEXP; e++) pos[e] = wbase[wid][e] + excl[e];
#pragma unroll
    for (int j = 0; j < 32; j++) {
        int e = loc[j];
        int p = pos[e]++;
        g_slot[tid * 32 + j] = (p < CAP) ? p : -1;
    }
}

// ---------------- 3. dispatch (gather tokens into [E,C,M]) ----------------
__global__ void gather_kernel(const float* __restrict__ x) {
    int t = blockIdx.x;
    int sl = g_slot[t];
    if (sl < 0) return;
    int e = g_idx[t];
    const float4* src = (const float4*)(x + (size_t)t * DMODEL);
    float4* dst = (float4*)(g_disp + ((size_t)e * CAP + sl) * DMODEL);
    dst[threadIdx.x] = src[threadIdx.x];
}

// ---------------- 4. per-expert SGEMM (R5 core: cp.async pipelined f32x2) ----------------
// 128x128 tile, K-depth 1024 per launch slab, 256 threads, 8x8 microtile.
// PHASE 1: g_disp @ w1 (+b1, relu) -> g_h            grid (N/128, 10, 8)
// PHASE 2: g_h[:, ks*1024:...] @ w2-slab -> g_part   grid (N/128, 10, 8*SPLITK), z = ks*8+e
template<int N, int LDA, bool RELU, int PHASE>
__global__ __launch_bounds__(256, 2)
void sgemm_kernel(const float* __restrict__ Bw, const float* __restrict__ biasb) {
    __shared__ float As[2][BK][PADW];
    __shared__ float Bs[2][BK][PADW];

    constexpr int KD = 1024;             // K depth per slab
    const int z  = blockIdx.z;
    const int e  = (PHASE == 1) ? z : (z & 7);
    const int ks = (PHASE == 1) ? 0 : (z >> 3);
    const int bm = blockIdx.y * 128;
    if (bm >= g_cnt[e]) return;          // expert under-filled: skip

    const float* A;
    float* Cc;
    if (PHASE == 1) {
        A  = g_disp + (size_t)e * CAP * DMODEL;
        Cc = g_h    + (size_t)e * CAP * DFF;
    } else {
        A  = g_h    + (size_t)e * CAP * DFF + (size_t)ks * KD;
        Cc = g_part + (size_t)z * CAP * DMODEL;
    }
    const float* B    = (PHASE == 1) ? (Bw + (size_t)e * KD * N)
                                     : (Bw + (size_t)e * DFF * N + (size_t)ks * KD * N);
    const float* bias = biasb + (size_t)e * N;

    const int bn = blockIdx.x * 128;
    const int tid = threadIdx.x;
    const int ty = tid >> 4, tx = tid & 15;
    constexpr int NCH = KD / BK;

    const int ar  = tid >> 1;
    const int ak0 = (tid & 1) * 8;
    const float* Aptr = A + (size_t)(bm + ar) * LDA + ak0;

    const int bk0  = tid >> 4;
    const int bseg = (tid * 2) & 31;
    const float* Bptr = B + (size_t)bk0 * N + bn + bseg * 4;
    u32 bs_s0 = smem_u32(&Bs[0][bk0][bseg * 4]);
    u32 bs_s1 = smem_u32(&Bs[1][bk0][bseg * 4]);

    float4 areg[2][2];
    areg[0][0] = *(const float4*)(Aptr);
    areg[0][1] = *(const float4*)(Aptr + 4);
    cpa16(bs_s0,      Bptr);
    cpa16(bs_s0 + 16, Bptr + 4);
    cpa_commit();
    areg[1][0] = *(const float4*)(Aptr + BK);
    areg[1][1] = *(const float4*)(Aptr + BK + 4);
    cpa16(bs_s1,      Bptr + (size_t)BK * N);
    cpa16(bs_s1 + 16, Bptr + (size_t)BK * N + 4);
    cpa_commit();

    ull acc[8][4];
#pragma unroll
    for (int i = 0; i < 8; i++)
#pragma unroll
        for (int j = 0; j < 4; j++) acc[i][j] = 0ull;

#pragma unroll 1
    for (int c = 0; c < NCH; c++) {
        if (c + 1 < NCH) cpa_wait1(); else cpa_wait0();
        const int s = c & 1;
#pragma unroll
        for (int q = 0; q < 2; q++) {
            float4 v = areg[s][q];
            int kq = ak0 + q * 4;
            As[s][kq + 0][ar] = v.x;
            As[s][kq + 1][ar] = v.y;
            As[s][kq + 2][ar] = v.z;
            As[s][kq + 3][ar] = v.w;
        }
        __syncthreads();
#pragma unroll
        for (int kk = 0; kk < BK; kk++) {
            float4 a0 = *(const float4*)&As[s][kk][ty * 8];
            float4 a1 = *(const float4*)&As[s][kk][ty * 8 + 4];
            float4 b0 = *(const float4*)&Bs[s][kk][tx * 8];
            float4 b1 = *(const float4*)&Bs[s][kk][tx * 8 + 4];
            ull bp0 = pk(b0.x, b0.y), bp1 = pk(b0.z, b0.w);
            ull bp2 = pk(b1.x, b1.y), bp3 = pk(b1.z, b1.w);
            float arr[8] = {a0.x, a0.y, a0.z, a0.w, a1.x, a1.y, a1.z, a1.w};
#pragma unroll
            for (int i = 0; i < 8; i++) {
                ull ap = pk(arr[i], arr[i]);
                acc[i][0] = ffma2(ap, bp0, acc[i][0]);
                acc[i][1] = ffma2(ap, bp1, acc[i][1]);
                acc[i][2] = ffma2(ap, bp2, acc[i][2]);
                acc[i][3] = ffma2(ap, bp3, acc[i][3]);
            }
        }
        __syncthreads();
        if (c + 2 < NCH) {
            const float* ap2 = Aptr + (size_t)(c + 2) * BK;
            areg[s][0] = *(const float4*)(ap2);
            areg[s][1] = *(const float4*)(ap2 + 4);
            const float* bp2g = Bptr + (size_t)(c + 2) * BK * N;
            u32 bss = s ? bs_s1 : bs_s0;
            cpa16(bss,      bp2g);
            cpa16(bss + 16, bp2g + 4);
            cpa_commit();
        }
    }

    // epilogue
    float bvals[8];
    if (PHASE == 1) {
#pragma unroll
        for (int j = 0; j < 8; j++) bvals[j] = bias[bn + tx * 8 + j];
    }
#pragma unroll
    for (int i = 0; i < 8; i++) {
        float o[8];
        upk(acc[i][0], o[0], o[1]);
        upk(acc[i][1], o[2], o[3]);
        upk(acc[i][2], o[4], o[5]);
        upk(acc[i][3], o[6], o[7]);
        if (PHASE == 1) {
#pragma unroll
            for (int j = 0; j < 8; j++) {
                float v = o[j] + bvals[j];
                if (RELU) v = fmaxf(v, 0.0f);
                o[j] = v;
            }
        }
        float* crow = Cc + (size_t)(bm + ty * 8 + i) * N + bn + tx * 8;
        *(float4*)crow       = make_float4(o[0], o[1], o[2], o[3]);
        *(float4*)(crow + 4) = make_float4(o[4], o[5], o[6], o[7]);
    }
}

// ---------------- 5. combine (+ split-K reduction, fixed order -> deterministic) ----------------
__global__ void combine_kernel(const float* __restrict__ b2, float* __restrict__ out) {
    int t = blockIdx.x;
    int sl = g_slot[t];
    float4* o = (float4*)(out + (size_t)t * DMODEL);
    int i = threadIdx.x;
    if (sl < 0) {
        o[i] = make_float4(0.f, 0.f, 0.f, 0.f);
        return;
    }
    float g = g_gate[t];
    int e = g_idx[t];
    const size_t stride = (size_t)NEXP * CAP * DMODEL;
    const float* p = g_part + ((size_t)e * CAP + sl) * DMODEL + i * 4;
    float4 s = *(const float4*)p;
#pragma unroll
    for (int ks = 1; ks < SPLITK; ks++) {
        float4 v = *(const float4*)(p + ks * stride);
        s.x += v.x; s.y += v.y; s.z += v.z; s.w += v.w;
    }
    float4 b = *(const float4*)(b2 + (size_t)e * DMODEL + i * 4);
    o[i] = make_float4((s.x + b.x) * g, (s.y + b.y) * g,
                       (s.z + b.z) * g, (s.w + b.w) * g);
}

// ---------------- launch ----------------
extern "C" void kernel_launch(void* const* d_in, const int* in_sizes, int n_in,
                              void* d_out, int out_size) {
    const float* x  = (const float*)d_in[0];   // [4,2048,1024]
    const float* wg = (const float*)d_in[1];   // [1024,8]
    const float* w1 = (const float*)d_in[2];   // [8,1024,4096]
    const float* b1 = (const float*)d_in[3];   // [8,4096]
    const float* w2 = (const float*)d_in[4];   // [8,4096,1024]
    const float* b2 = (const float*)d_in[5];   // [8,1024]
    float* out = (float*)d_out;                // [4,2048,1024]

    gate_kernel<<<T_TOK / 8, 256>>>(x, wg);
    scan_kernel<<<1, 256>>>();
    gather_kernel<<<T_TOK, 256>>>(x);
    // GEMM1: full K=1024 per block
    sgemm_kernel<DFF, DMODEL, true, 1>
        <<<dim3(DFF / 128, CAP / 128, NEXP), 256>>>(w1, b1);
    // GEMM2: split-K=4 slabs of 1024 -> partials
    sgemm_kernel<DMODEL, DFF, false, 2>
        <<<dim3(DMODEL / 128, CAP / 128, NEXP * SPLITK), 256>>>(w2, nullptr);
    combine_kernel<<<T_TOK, 256>>>(b2, out);
}

// round 8
// speedup vs baseline: 1.4291x; 1.0110x over previous
#include <cuda_runtime.h>

#define T_TOK   8192
#define DMODEL  1024
#define NEXP    8
#define DFF     4096
#define CAP     1280   // int(1.25 * 8192 / 8)
#define BK      16
#define PADW    132
#define SPLITK  4

typedef unsigned int u32;
typedef unsigned long long ull;

// ---------------- scratch (device globals; no allocation) ----------------
__device__ float g_disp[(size_t)NEXP * CAP * DMODEL];              // 40 MB
__device__ float g_h   [(size_t)NEXP * CAP * DFF];                 // 167 MB
__device__ float g_part[(size_t)SPLITK * NEXP * CAP * DMODEL];     // 160 MB
__device__ int   g_idx [T_TOK];
__device__ float g_gate[T_TOK];
__device__ int   g_slot[T_TOK];
__device__ int   g_cnt [NEXP];

// ---------------- packed f32x2 + async-copy helpers ----------------
__device__ __forceinline__ ull pk(float x, float y) {
    ull r; asm("mov.b64 %0, {%1, %2};" : "=l"(r) : "f"(x), "f"(y)); return r;
}
__device__ __forceinline__ void upk(ull v, float& x, float& y) {
    asm("mov.b64 {%0, %1}, %2;" : "=f"(x), "=f"(y) : "l"(v));
}
__device__ __forceinline__ ull ffma2(ull a, ull b, ull c) {
    ull d; asm("fma.rn.f32x2 %0, %1, %2, %3;" : "=l"(d) : "l"(a), "l"(b), "l"(c)); return d;
}
__device__ __forceinline__ u32 smem_u32(const void* p) {
    u32 a; asm("{ .reg .u64 t; cvta.to.shared.u64 t, %1; cvt.u32.u64 %0, t; }" : "=r"(a) : "l"(p));
    return a;
}
__device__ __forceinline__ void cpa16(u32 s, const void* g) {
    asm volatile("cp.async.cg.shared.global [%0], [%1], 16;" :: "r"(s), "l"(g));
}
__device__ __forceinline__ void cpa_commit() { asm volatile("cp.async.commit_group;" ::: "memory"); }
__device__ __forceinline__ void cpa_wait1()  { asm volatile("cp.async.wait_group 1;" ::: "memory"); }
__device__ __forceinline__ void cpa_wait0()  { asm volatile("cp.async.wait_group 0;" ::: "memory"); }

// ---------------- 1. gating ----------------
__global__ void gate_kernel(const float* __restrict__ x, const float* __restrict__ wg) {
    __shared__ float wgT[NEXP][DMODEL];
    int tid = threadIdx.x;
    for (int i = tid; i < DMODEL * NEXP; i += 256)
        wgT[i & 7][i >> 3] = wg[i];
    __syncthreads();
    int warp = tid >> 5, lane = tid & 31;
    int t = blockIdx.x * 8 + warp;
    const float* xr = x + (size_t)t * DMODEL;
    float acc[NEXP];
#pragma unroll
    for (int e = 0; e < NEXP; e++) acc[e] = 0.0f;
    for (int m = lane; m < DMODEL; m += 32) {
        float xv = xr[m];
#pragma unroll
        for (int e = 0; e < NEXP; e++) acc[e] += xv * wgT[e][m];
    }
#pragma unroll
    for (int e = 0; e < NEXP; e++)
#pragma unroll
        for (int o = 16; o; o >>= 1)
            acc[e] += __shfl_xor_sync(0xffffffffu, acc[e], o);
    if (lane == 0) {
        float mx = acc[0]; int a = 0;
#pragma unroll
        for (int e = 1; e < NEXP; e++)
            if (acc[e] > mx) { mx = acc[e]; a = e; }   // first-max, matches jnp.argmax
        float s = 0.0f;
#pragma unroll
        for (int e = 0; e < NEXP; e++) s += expf(acc[e] - mx);
        g_idx[t]  = a;
        g_gate[t] = 1.0f / s;
    }
}

// ---------------- 2. queue positions + per-expert counts ----------------
__global__ void scan_kernel() {
    __shared__ int wsum[8][NEXP];
    __shared__ int wbase[8][NEXP];
    int tid = threadIdx.x, wid = tid >> 5, lane = tid & 31;
    int loc[32];
    const int4* gp = (const int4*)(g_idx + tid * 32);
#pragma unroll
    for (int v = 0; v < 8; v++) {
        int4 q = gp[v];
        loc[v * 4 + 0] = q.x; loc[v * 4 + 1] = q.y;
        loc[v * 4 + 2] = q.z; loc[v * 4 + 3] = q.w;
    }
    int cnt[NEXP];
#pragma unroll
    for (int e = 0; e < NEXP; e++) cnt[e] = 0;
#pragma unroll
    for (int j = 0; j < 32; j++) cnt[loc[j]]++;
    int excl[NEXP];
#pragma unroll
    for (int e = 0; e < NEXP; e++) {
        int inc = cnt[e];
#pragma unroll
        for (int off = 1; off < 32; off <<= 1) {
            int n = __shfl_up_sync(0xffffffffu, inc, off);
            if (lane >= off) inc += n;
        }
        excl[e] = inc - cnt[e];
        if (lane == 31) wsum[wid][e] = inc;
    }
    __syncthreads();
    if (tid == 0) {
#pragma unroll
        for (int e = 0; e < NEXP; e++) {
            int run = 0;
            for (int w = 0; w < 8; w++) { wbase[w][e] = run; run += wsum[w][e]; }
            g_cnt[e] = (run < CAP) ? run : CAP;
        }
    }
    __syncthreads();
    int pos[NEXP];
#pragma unroll
    for (int e = 0; e < NEXP; e++) pos[e] = wbase[wid][e] + excl[e];
#pragma unroll
    for (int j = 0; j < 32; j++) {
        int e = loc[j];
        int p = pos[e]++;
        g_slot[tid * 32 + j] = (p < CAP) ? p : -1;
    }
}

// ---------------- 3. dispatch (gather tokens into [E,C,M]) ----------------
__global__ void gather_kernel(const float* __restrict__ x) {
    int t = blockIdx.x;
    int sl = g_slot[t];
    if (sl < 0) return;
    int e = g_idx[t];
    const float4* src = (const float4*)(x + (size_t)t * DMODEL);
    float4* dst = (float4*)(g_disp + ((size_t)e * CAP + sl) * DMODEL);
    dst[threadIdx.x] = src[threadIdx.x];
}

// ---------------- 4. per-expert SGEMM: single-barrier-per-chunk pipeline ----------------
// 128x128 tile, K slab 1024, 256 threads, 8x8 microtile, packed f32x2 FMA.
// As double-buffered (reg-staged), Bs TRIPLE-buffered (cp.async), ONE __syncthreads per chunk.
// PHASE 1: g_disp @ w1 (+b1, relu) -> g_h            grid (N/128, 10, 8)
// PHASE 2: g_h[:, ks*1024:] @ w2-slab -> g_part      grid (N/128, 10, 8*SPLITK), z = ks*8+e
template<int N, int LDA, bool RELU, int PHASE>
__global__ __launch_bounds__(256, 2)
void sgemm_kernel(const float* __restrict__ Bw, const float* __restrict__ biasb) {
    __shared__ float As[2][BK][PADW];
    __shared__ float Bs[3][BK][PADW];

    constexpr int KD = 1024;             // K depth per slab
    const int z  = blockIdx.z;
    const int e  = (PHASE == 1) ? z : (z & 7);
    const int ks = (PHASE == 1) ? 0 : (z >> 3);
    const int bm = blockIdx.y * 128;
    if (bm >= g_cnt[e]) return;          // expert under-filled: skip

    const float* A;
    float* Cc;
    if (PHASE == 1) {
        A  = g_disp + (size_t)e * CAP * DMODEL;
        Cc = g_h    + (size_t)e * CAP * DFF;
    } else {
        A  = g_h    + (size_t)e * CAP * DFF + (size_t)ks * KD;
        Cc = g_part + (size_t)z * CAP * DMODEL;
    }
    const float* B    = (PHASE == 1) ? (Bw + (size_t)e * KD * N)
                                     : (Bw + (size_t)e * DFF * N + (size_t)ks * KD * N);
    const float* bias = biasb + (size_t)e * N;

    const int bn = blockIdx.x * 128;
    const int tid = threadIdx.x;
    const int ty = tid >> 4, tx = tid & 15;
    constexpr int NCH = KD / BK;

    const int ar  = tid >> 1;
    const int ak0 = (tid & 1) * 8;
    const float* Aptr = A + (size_t)(bm + ar) * LDA + ak0;

    const int bk0  = tid >> 4;
    const int bseg = (tid * 2) & 31;
    const float* Bptr = B + (size_t)bk0 * N + bn + bseg * 4;
    u32 bs_st[3] = { smem_u32(&Bs[0][bk0][bseg * 4]),
                     smem_u32(&Bs[1][bk0][bseg * 4]),
                     smem_u32(&Bs[2][bk0][bseg * 4]) };

    // prologue: A(0), A(1) in regs; B(0), B(1) in flight
    float4 areg[2][2];
    areg[0][0] = *(const float4*)(Aptr);
    areg[0][1] = *(const float4*)(Aptr + 4);
    cpa16(bs_st[0],      Bptr);
    cpa16(bs_st[0] + 16, Bptr + 4);
    cpa_commit();
    areg[1][0] = *(const float4*)(Aptr + BK);
    areg[1][1] = *(const float4*)(Aptr + BK + 4);
    cpa16(bs_st[1],      Bptr + (size_t)BK * N);
    cpa16(bs_st[1] + 16, Bptr + (size_t)BK * N + 4);
    cpa_commit();

    ull acc[8][4];
#pragma unroll
    for (int i = 0; i < 8; i++)
#pragma unroll
        for (int j = 0; j < 4; j++) acc[i][j] = 0ull;

#pragma unroll 1
    for (int c = 0; c < NCH; c++) {
        const int sa = c & 1;
        // store A chunk c (already in regs) transposed into As[sa].
        // Safe pre-barrier: all readers of As[sa] (chunk c-2) finished before barrier c-1.
#pragma unroll
        for (int q = 0; q < 2; q++) {
            float4 v = areg[sa][q];
            int kq = ak0 + q * 4;
            As[sa][kq + 0][ar] = v.x;
            As[sa][kq + 1][ar] = v.y;
            As[sa][kq + 2][ar] = v.z;
            As[sa][kq + 3][ar] = v.w;
        }
        if (c + 1 < NCH) cpa_wait1(); else cpa_wait0();   // B(c) landed
        __syncthreads();                                  // As[sa] + Bs[c%3] visible to all
        const int sb = c % 3;
#pragma unroll
        for (int kk = 0; kk < BK; kk++) {
            float4 a0 = *(const float4*)&As[sa][kk][ty * 8];
            float4 a1 = *(const float4*)&As[sa][kk][ty * 8 + 4];
            float4 b0 = *(const float4*)&Bs[sb][kk][tx * 8];
            float4 b1 = *(const float4*)&Bs[sb][kk][tx * 8 + 4];
            ull bp0 = pk(b0.x, b0.y), bp1 = pk(b0.z, b0.w);
            ull bp2 = pk(b1.x, b1.y), bp3 = pk(b1.z, b1.w);
            float arr[8] = {a0.x, a0.y, a0.z, a0.w, a1.x, a1.y, a1.z, a1.w};
#pragma unroll
            for (int i = 0; i < 8; i++) {
                ull ap = pk(arr[i], arr[i]);
                acc[i][0] = ffma2(ap, bp0, acc[i][0]);
                acc[i][1] = ffma2(ap, bp1, acc[i][1]);
                acc[i][2] = ffma2(ap, bp2, acc[i][2]);
                acc[i][3] = ffma2(ap, bp3, acc[i][3]);
            }
        }
        // post-compute: prefetch chunk c+2 (A -> regs, B -> Bs[(c+2)%3]).
        // Bs[(c+2)%3] != Bs[c%3] (being read this window) and != Bs[(c+1)%3] (next window).
        if (c + 2 < NCH) {
            const float* ap2 = Aptr + (size_t)(c + 2) * BK;
            areg[sa][0] = *(const float4*)(ap2);
            areg[sa][1] = *(const float4*)(ap2 + 4);
            const float* bp2g = Bptr + (size_t)(c + 2) * BK * N;
            u32 bss = bs_st[(c + 2) % 3];
            cpa16(bss,      bp2g);
            cpa16(bss + 16, bp2g + 4);
            cpa_commit();
        }
    }

    // epilogue
    float bvals[8];
    if (PHASE == 1) {
#pragma unroll
        for (int j = 0; j < 8; j++) bvals[j] = bias[bn + tx * 8 + j];
    }
#pragma unroll
    for (int i = 0; i < 8; i++) {
        float o[8];
        upk(acc[i][0], o[0], o[1]);
        upk(acc[i][1], o[2], o[3]);
        upk(acc[i][2], o[4], o[5]);
        upk(acc[i][3], o[6], o[7]);
        if (PHASE == 1) {
#pragma unroll
            for (int j = 0; j < 8; j++) {
                float v = o[j] + bvals[j];
                if (RELU) v = fmaxf(v, 0.0f);
                o[j] = v;
            }
        }
        float* crow = Cc + (size_t)(bm + ty * 8 + i) * N + bn + tx * 8;
        *(float4*)crow       = make_float4(o[0], o[1], o[2], o[3]);
        *(float4*)(crow + 4) = make_float4(o[4], o[5], o[6], o[7]);
    }
}

// ---------------- 5. combine (+ split-K reduction, fixed order -> deterministic) ----------------
__global__ void combine_kernel(const float* __restrict__ b2, float* __restrict__ out) {
    int t = blockIdx.x;
    int sl = g_slot[t];
    float4* o = (float4*)(out + (size_t)t * DMODEL);
    int i = threadIdx.x;
    if (sl < 0) {
        o[i] = make_float4(0.f, 0.f, 0.f, 0.f);
        return;
    }
    float g = g_gate[t];
    int e = g_idx[t];
    const size_t stride = (size_t)NEXP * CAP * DMODEL;
    const float* p = g_part + ((size_t)e * CAP + sl) * DMODEL + i * 4;
    float4 s = *(const float4*)p;
#pragma unroll
    for (int ks = 1; ks < SPLITK; ks++) {
        float4 v = *(const float4*)(p + ks * stride);
        s.x += v.x; s.y += v.y; s.z += v.z; s.w += v.w;
    }
    float4 b = *(const float4*)(b2 + (size_t)e * DMODEL + i * 4);
    o[i] = make_float4((s.x + b.x) * g, (s.y + b.y) * g,
                       (s.z + b.z) * g, (s.w + b.w) * g);
}

// ---------------- launch ----------------
extern "C" void kernel_launch(void* const* d_in, const int* in_sizes, int n_in,
                              void* d_out, int out_size) {
    const float* x  = (const float*)d_in[0];   // [4,2048,1024]
    const float* wg = (const float*)d_in[1];   // [1024,8]
    const float* w1 = (const float*)d_in[2];   // [8,1024,4096]
    const float* b1 = (const float*)d_in[3];   // [8,4096]
    const float* w2 = (const float*)d_in[4];   // [8,4096,1024]
    const float* b2 = (const float*)d_in[5];   // [8,1024]
    float* out = (float*)d_out;                // [4,2048,1024]

    gate_kernel<<<T_TOK / 8, 256>>>(x, wg);
    scan_kernel<<<1, 256>>>();
    gather_kernel<<<T_TOK, 256>>>(x);
    // GEMM1: full K=1024 per block
    sgemm_kernel<DFF, DMODEL, true, 1>
        <<<dim3(DFF / 128, CAP / 128, NEXP), 256>>>(w1, b1);
    // GEMM2: split-K=4 slabs of 1024 -> partials
    sgemm_kernel<DMODEL, DFF, false, 2>
        <<<dim3(DMODEL / 128, CAP / 128, NEXP * SPLITK), 256>>>(w2, nullptr);
    combine_kernel<<<T_TOK, 256>>>(b2, out);
}

// round 9
// speedup vs baseline: 1.5909x; 1.1132x over previous
#include <cuda_runtime.h>

#define T_TOK   8192
#define DMODEL  1024
#define NEXP    8
#define DFF     4096
#define CAP     1280   // int(1.25 * 8192 / 8)
#define BK      16
#define PADW    132
#define SPLITK  4

typedef unsigned int u32;
typedef unsigned long long ull;

// ---------------- scratch (device globals; no allocation) ----------------
__device__ float g_disp[(size_t)NEXP * CAP * DMODEL];              // 40 MB
__device__ float g_h   [(size_t)NEXP * CAP * DFF];                 // 167 MB
__device__ float g_part[(size_t)SPLITK * NEXP * CAP * DMODEL];     // 160 MB
__device__ int   g_idx [T_TOK];
__device__ float g_gate[T_TOK];
__device__ int   g_slot[T_TOK];
__device__ int   g_cnt [NEXP];

// ---------------- packed f32x2 + async-copy helpers ----------------
__device__ __forceinline__ ull pk(float x, float y) {
    ull r; asm("mov.b64 %0, {%1, %2};" : "=l"(r) : "f"(x), "f"(y)); return r;
}
__device__ __forceinline__ void upk(ull v, float& x, float& y) {
    asm("mov.b64 {%0, %1}, %2;" : "=f"(x), "=f"(y) : "l"(v));
}
__device__ __forceinline__ ull ffma2(ull a, ull b, ull c) {
    ull d; asm("fma.rn.f32x2 %0, %1, %2, %3;" : "=l"(d) : "l"(a), "l"(b), "l"(c)); return d;
}
__device__ __forceinline__ u32 smem_u32(const void* p) {
    u32 a; asm("{ .reg .u64 t; cvta.to.shared.u64 t, %1; cvt.u32.u64 %0, t; }" : "=r"(a) : "l"(p));
    return a;
}
__device__ __forceinline__ void cpa16(u32 s, const void* g) {
    asm volatile("cp.async.cg.shared.global [%0], [%1], 16;" :: "r"(s), "l"(g));
}
__device__ __forceinline__ void cpa_commit() { asm volatile("cp.async.commit_group;" ::: "memory"); }
__device__ __forceinline__ void cpa_wait1()  { asm volatile("cp.async.wait_group 1;" ::: "memory"); }
__device__ __forceinline__ void cpa_wait0()  { asm volatile("cp.async.wait_group 0;" ::: "memory"); }

// ---------------- 1. gating ----------------
__global__ void gate_kernel(const float* __restrict__ x, const float* __restrict__ wg) {
    __shared__ float wgT[NEXP][DMODEL];
    int tid = threadIdx.x;
    for (int i = tid; i < DMODEL * NEXP; i += 256)
        wgT[i & 7][i >> 3] = wg[i];
    __syncthreads();
    int warp = tid >> 5, lane = tid & 31;
    int t = blockIdx.x * 8 + warp;
    const float* xr = x + (size_t)t * DMODEL;
    float acc[NEXP];
#pragma unroll
    for (int e = 0; e < NEXP; e++) acc[e] = 0.0f;
    for (int m = lane; m < DMODEL; m += 32) {
        float xv = xr[m];
#pragma unroll
        for (int e = 0; e < NEXP; e++) acc[e] += xv * wgT[e][m];
    }
#pragma unroll
    for (int e = 0; e < NEXP; e++)
#pragma unroll
        for (int o = 16; o; o >>= 1)
            acc[e] += __shfl_xor_sync(0xffffffffu, acc[e], o);
    if (lane == 0) {
        float mx = acc[0]; int a = 0;
#pragma unroll
        for (int e = 1; e < NEXP; e++)
            if (acc[e] > mx) { mx = acc[e]; a = e; }   // first-max, matches jnp.argmax
        float s = 0.0f;
#pragma unroll
        for (int e = 0; e < NEXP; e++) s += expf(acc[e] - mx);
        g_idx[t]  = a;
        g_gate[t] = 1.0f / s;
    }
}

// ---------------- 2. queue positions + per-expert counts ----------------
__global__ void scan_kernel() {
    __shared__ int wsum[8][NEXP];
    __shared__ int wbase[8][NEXP];
    int tid = threadIdx.x, wid = tid >> 5, lane = tid & 31;
    int loc[32];
    const int4* gp = (const int4*)(g_idx + tid * 32);
#pragma unroll
    for (int v = 0; v < 8; v++) {
        int4 q = gp[v];
        loc[v * 4 + 0] = q.x; loc[v * 4 + 1] = q.y;
        loc[v * 4 + 2] = q.z; loc[v * 4 + 3] = q.w;
    }
    int cnt[NEXP];
#pragma unroll
    for (int e = 0; e < NEXP; e++) cnt[e] = 0;
#pragma unroll
    for (int j = 0; j < 32; j++) cnt[loc[j]]++;
    int excl[NEXP];
#pragma unroll
    for (int e = 0; e < NEXP; e++) {
        int inc = cnt[e];
#pragma unroll
        for (int off = 1; off < 32; off <<= 1) {
            int n = __shfl_up_sync(0xffffffffu, inc, off);
            if (lane >= off) inc += n;
        }
        excl[e] = inc - cnt[e];
        if (lane == 31) wsum[wid][e] = inc;
    }
    __syncthreads();
    if (tid == 0) {
#pragma unroll
        for (int e = 0; e < NEXP; e++) {
            int run = 0;
            for (int w = 0; w < 8; w++) { wbase[w][e] = run; run += wsum[w][e]; }
            g_cnt[e] = (run < CAP) ? run : CAP;
        }
    }
    __syncthreads();
    int pos[NEXP];
#pragma unroll
    for (int e = 0; e < NEXP; e++) pos[e] = wbase[wid][e] + excl[e];
#pragma unroll
    for (int j = 0; j < 32; j++) {
        int e = loc[j];
        int p = pos[e]++;
        g_slot[tid * 32 + j] = (p < CAP) ? p : -1;
    }
}

// ---------------- 3. dispatch (gather tokens into [E,C,M]) ----------------
__global__ void gather_kernel(const float* __restrict__ x) {
    int t = blockIdx.x;
    int sl = g_slot[t];
    if (sl < 0) return;
    int e = g_idx[t];
    const float4* src = (const float4*)(x + (size_t)t * DMODEL);
    float4* dst = (float4*)(g_disp + ((size_t)e * CAP + sl) * DMODEL);
    dst[threadIdx.x] = src[threadIdx.x];
}

// ---------------- 4. per-expert SGEMM: LDS-wavefront-minimized warp shape ----------------
// 128x128 tile, K slab 1024, 256 threads, 8x8 microtile, packed f32x2 FMA.
// Warp shape 8 lty x 4 ltx (warp tile 64x32): B-frag = 1 wavefront/load, A-frag = 2.
// B-frags read directly as ulonglong2 (adjacent floats == packed pair; zero-cost packing).
// As double-buffered (reg-staged), Bs triple-buffered (cp.async), one barrier per chunk.
template<int N, int LDA, bool RELU, int PHASE>
__global__ __launch_bounds__(256, 2)
void sgemm_kernel(const float* __restrict__ Bw, const float* __restrict__ biasb) {
    __shared__ __align__(16) float As[2][BK][PADW];
    __shared__ __align__(16) float Bs[3][BK][PADW];

    constexpr int KD = 1024;             // K depth per slab
    const int z  = blockIdx.z;
    const int e  = (PHASE == 1) ? z : (z & 7);
    const int ks = (PHASE == 1) ? 0 : (z >> 3);
    const int bm = blockIdx.y * 128;
    if (bm >= g_cnt[e]) return;          // expert under-filled: skip

    const float* A;
    float* Cc;
    if (PHASE == 1) {
        A  = g_disp + (size_t)e * CAP * DMODEL;
        Cc = g_h    + (size_t)e * CAP * DFF;
    } else {
        A  = g_h    + (size_t)e * CAP * DFF + (size_t)ks * KD;
        Cc = g_part + (size_t)z * CAP * DMODEL;
    }
    const float* B    = (PHASE == 1) ? (Bw + (size_t)e * KD * N)
                                     : (Bw + (size_t)e * DFF * N + (size_t)ks * KD * N);
    const float* bias = biasb + (size_t)e * N;

    const int bn = blockIdx.x * 128;
    const int tid = threadIdx.x;
    const int wid = tid >> 5, lane = tid & 31;
    // warp-shape remap: 8 warps as 2 (row) x 4 (col); lanes as 8 (row) x 4 (col)
    const int ty = (wid >> 2) * 8 + (lane >> 2);   // 0..15
    const int tx = (wid & 3) * 4 + (lane & 3);     // 0..15
    constexpr int NCH = KD / BK;

    const int ar  = tid >> 1;
    const int ak0 = (tid & 1) * 8;
    const float* Aptr = A + (size_t)(bm + ar) * LDA + ak0;

    const int bk0  = tid >> 4;
    const int bseg = (tid * 2) & 31;
    const float* Bptr = B + (size_t)bk0 * N + bn + bseg * 4;
    u32 bs_st[3] = { smem_u32(&Bs[0][bk0][bseg * 4]),
                     smem_u32(&Bs[1][bk0][bseg * 4]),
                     smem_u32(&Bs[2][bk0][bseg * 4]) };

    // prologue: A(0), A(1) in regs; B(0), B(1) in flight
    float4 areg[2][2];
    areg[0][0] = *(const float4*)(Aptr);
    areg[0][1] = *(const float4*)(Aptr + 4);
    cpa16(bs_st[0],      Bptr);
    cpa16(bs_st[0] + 16, Bptr + 4);
    cpa_commit();
    areg[1][0] = *(const float4*)(Aptr + BK);
    areg[1][1] = *(const float4*)(Aptr + BK + 4);
    cpa16(bs_st[1],      Bptr + (size_t)BK * N);
    cpa16(bs_st[1] + 16, Bptr + (size_t)BK * N + 4);
    cpa_commit();

    ull acc[8][4];
#pragma unroll
    for (int i = 0; i < 8; i++)
#pragma unroll
        for (int j = 0; j < 4; j++) acc[i][j] = 0ull;

#pragma unroll 1
    for (int c = 0; c < NCH; c++) {
        const int sa = c & 1;
        // store A chunk c (in regs) transposed into As[sa]; safe pre-barrier
        // (readers of As[sa] finished before the previous barrier).
#pragma unroll
        for (int q = 0; q < 2; q++) {
            float4 v = areg[sa][q];
            int kq = ak0 + q * 4;
            As[sa][kq + 0][ar] = v.x;
            As[sa][kq + 1][ar] = v.y;
            As[sa][kq + 2][ar] = v.z;
            As[sa][kq + 3][ar] = v.w;
        }
        if (c + 1 < NCH) cpa_wait1(); else cpa_wait0();   // B(c) landed
        __syncthreads();                                  // As[sa] + Bs[c%3] visible
        const int sb = c % 3;
#pragma unroll
        for (int kk = 0; kk < BK; kk++) {
            float4 a0 = *(const float4*)&As[sa][kk][ty * 8];
            float4 a1 = *(const float4*)&As[sa][kk][ty * 8 + 4];
            const ull* brow = (const ull*)&Bs[sb][kk][tx * 8];
            ulonglong2 B0 = *(const ulonglong2*)(brow);       // (b0,b1),(b2,b3)
            ulonglong2 B1 = *(const ulonglong2*)(brow + 2);   // (b4,b5),(b6,b7)
            ull bp0 = B0.x, bp1 = B0.y, bp2 = B1.x, bp3 = B1.y;
            float arr[8] = {a0.x, a0.y, a0.z, a0.w, a1.x, a1.y, a1.z, a1.w};
#pragma unroll
            for (int i = 0; i < 8; i++) {
                ull ap = pk(arr[i], arr[i]);
                acc[i][0] = ffma2(ap, bp0, acc[i][0]);
                acc[i][1] = ffma2(ap, bp1, acc[i][1]);
                acc[i][2] = ffma2(ap, bp2, acc[i][2]);
                acc[i][3] = ffma2(ap, bp3, acc[i][3]);
            }
        }
        // post-compute: prefetch chunk c+2 (A -> regs, B -> Bs[(c+2)%3]).
        if (c + 2 < NCH) {
            const float* ap2 = Aptr + (size_t)(c + 2) * BK;
            areg[sa][0] = *(const float4*)(ap2);
            areg[sa][1] = *(const float4*)(ap2 + 4);
            const float* bp2g = Bptr + (size_t)(c + 2) * BK * N;
            u32 bss = bs_st[(c + 2) % 3];
            cpa16(bss,      bp2g);
            cpa16(bss + 16, bp2g + 4);
            cpa_commit();
        }
    }

    // epilogue
    float bvals[8];
    if (PHASE == 1) {
#pragma unroll
        for (int j = 0; j < 8; j++) bvals[j] = bias[bn + tx * 8 + j];
    }
#pragma unroll
    for (int i = 0; i < 8; i++) {
        float o[8];
        upk(acc[i][0], o[0], o[1]);
        upk(acc[i][1], o[2], o[3]);
        upk(acc[i][2], o[4], o[5]);
        upk(acc[i][3], o[6], o[7]);
        if (PHASE == 1) {
#pragma unroll
            for (int j = 0; j < 8; j++) {
                float v = o[j] + bvals[j];
                if (RELU) v = fmaxf(v, 0.0f);
                o[j] = v;
            }
        }
        float* crow = Cc + (size_t)(bm + ty * 8 + i) * N + bn + tx * 8;
        *(float4*)crow       = make_float4(o[0], o[1], o[2], o[3]);
        *(float4*)(crow + 4) = make_float4(o[4], o[5], o[6], o[7]);
    }
}

// ---------------- 5. combine (+ split-K reduction, fixed order -> deterministic) ----------------
__global__ void combine_kernel(const float* __restrict__ b2, float* __restrict__ out) {
    int t = blockIdx.x;
    int sl = g_slot[t];
    float4* o = (float4*)(out + (size_t)t * DMODEL);
    int i = threadIdx.x;
    if (sl < 0) {
        o[i] = make_float4(0.f, 0.f, 0.f, 0.f);
        return;
    }
    float g = g_gate[t];
    int e = g_idx[t];
    const size_t stride = (size_t)NEXP * CAP * DMODEL;
    const float* p = g_part + ((size_t)e * CAP + sl) * DMODEL + i * 4;
    float4 s = *(const float4*)p;
#pragma unroll
    for (int ks = 1; ks < SPLITK; ks++) {
        float4 v = *(const float4*)(p + ks * stride);
        s.x += v.x; s.y += v.y; s.z += v.z; s.w += v.w;
    }
    float4 b = *(const float4*)(b2 + (size_t)e * DMODEL + i * 4);
    o[i] = make_float4((s.x + b.x) * g, (s.y + b.y) * g,
                       (s.z + b.z) * g, (s.w + b.w) * g);
}

// ---------------- launch ----------------
extern "C" void kernel_launch(void* const* d_in, const int* in_sizes, int n_in,
                              void* d_out, int out_size) {
    const float* x  = (const float*)d_in[0];   // [4,2048,1024]
    const float* wg = (const float*)d_in[1];   // [1024,8]
    const float* w1 = (const float*)d_in[2];   // [8,1024,4096]
    const float* b1 = (const float*)d_in[3];   // [8,4096]
    const float* w2 = (const float*)d_in[4];   // [8,4096,1024]
    const float* b2 = (const float*)d_in[5];   // [8,1024]
    float* out = (float*)d_out;                // [4,2048,1024]

    gate_kernel<<<T_TOK / 8, 256>>>(x, wg);
    scan_kernel<<<1, 256>>>();
    gather_kernel<<<T_TOK, 256>>>(x);
    // GEMM1: full K=1024 per block
    sgemm_kernel<DFF, DMODEL, true, 1>
        <<<dim3(DFF / 128, CAP / 128, NEXP), 256>>>(w1, b1);
    // GEMM2: split-K=4 slabs of 1024 -> partials
    sgemm_kernel<DMODEL, DFF, false, 2>
        <<<dim3(DMODEL / 128, CAP / 128, NEXP * SPLITK), 256>>>(w2, nullptr);
    combine_kernel<<<T_TOK, 256>>>(b2, out);
}

// round 10
// speedup vs baseline: 1.6315x; 1.0255x over previous
#include <cuda_runtime.h>

#define T_TOK   8192
#define DMODEL  1024
#define NEXP    8
#define DFF     4096
#define CAP     1280   // int(1.25 * 8192 / 8)
#define BK      16
#define PADW    132
#define SPLITK  4

typedef unsigned int u32;
typedef unsigned long long ull;

// ---------------- scratch (device globals; no allocation) ----------------
__device__ float g_disp[(size_t)NEXP * CAP * DMODEL];              // 40 MB
__device__ float g_h   [(size_t)NEXP * CAP * DFF];                 // 167 MB
__device__ float g_part[(size_t)SPLITK * NEXP * CAP * DMODEL];     // 160 MB
__device__ int   g_idx [T_TOK];
__device__ float g_gate[T_TOK];
__device__ int   g_slot[T_TOK];
__device__ int   g_cnt [NEXP];

// ---------------- packed f32x2 + async-copy helpers ----------------
__device__ __forceinline__ ull pk(float x, float y) {
    ull r; asm("mov.b64 %0, {%1, %2};" : "=l"(r) : "f"(x), "f"(y)); return r;
}
__device__ __forceinline__ void upk(ull v, float& x, float& y) {
    asm("mov.b64 {%0, %1}, %2;" : "=f"(x), "=f"(y) : "l"(v));
}
__device__ __forceinline__ ull ffma2(ull a, ull b, ull c) {
    ull d; asm("fma.rn.f32x2 %0, %1, %2, %3;" : "=l"(d) : "l"(a), "l"(b), "l"(c)); return d;
}
__device__ __forceinline__ u32 smem_u32(const void* p) {
    u32 a; asm("{ .reg .u64 t; cvta.to.shared.u64 t, %1; cvt.u32.u64 %0, t; }" : "=r"(a) : "l"(p));
    return a;
}
__device__ __forceinline__ void cpa16(u32 s, const void* g) {
    asm volatile("cp.async.cg.shared.global [%0], [%1], 16;" :: "r"(s), "l"(g));
}
__device__ __forceinline__ void cpa_commit() { asm volatile("cp.async.commit_group;" ::: "memory"); }
__device__ __forceinline__ void cpa_wait1()  { asm volatile("cp.async.wait_group 1;" ::: "memory"); }
__device__ __forceinline__ void cpa_wait0()  { asm volatile("cp.async.wait_group 0;" ::: "memory"); }

// ---------------- 1. gating ----------------
__global__ void gate_kernel(const float* __restrict__ x, const float* __restrict__ wg) {
    __shared__ float wgT[NEXP][DMODEL];
    int tid = threadIdx.x;
    for (int i = tid; i < DMODEL * NEXP; i += 256)
        wgT[i & 7][i >> 3] = wg[i];
    __syncthreads();
    int warp = tid >> 5, lane = tid & 31;
    int t = blockIdx.x * 8 + warp;
    const float* xr = x + (size_t)t * DMODEL;
    float acc[NEXP];
#pragma unroll
    for (int e = 0; e < NEXP; e++) acc[e] = 0.0f;
    for (int m = lane; m < DMODEL; m += 32) {
        float xv = xr[m];
#pragma unroll
        for (int e = 0; e < NEXP; e++) acc[e] += xv * wgT[e][m];
    }
#pragma unroll
    for (int e = 0; e < NEXP; e++)
#pragma unroll
        for (int o = 16; o; o >>= 1)
            acc[e] += __shfl_xor_sync(0xffffffffu, acc[e], o);
    if (lane == 0) {
        float mx = acc[0]; int a = 0;
#pragma unroll
        for (int e = 1; e < NEXP; e++)
            if (acc[e] > mx) { mx = acc[e]; a = e; }   // first-max, matches jnp.argmax
        float s = 0.0f;
#pragma unroll
        for (int e = 0; e < NEXP; e++) s += expf(acc[e] - mx);
        g_idx[t]  = a;
        g_gate[t] = 1.0f / s;
    }
}

// ---------------- 2. queue positions + per-expert counts ----------------
__global__ void scan_kernel() {
    __shared__ int wsum[8][NEXP];
    __shared__ int wbase[8][NEXP];
    int tid = threadIdx.x, wid = tid >> 5, lane = tid & 31;
    int loc[32];
    const int4* gp = (const int4*)(g_idx + tid * 32);
#pragma unroll
    for (int v = 0; v < 8; v++) {
        int4 q = gp[v];
        loc[v * 4 + 0] = q.x; loc[v * 4 + 1] = q.y;
        loc[v * 4 + 2] = q.z; loc[v * 4 + 3] = q.w;
    }
    int cnt[NEXP];
#pragma unroll
    for (int e = 0; e < NEXP; e++) cnt[e] = 0;
#pragma unroll
    for (int j = 0; j < 32; j++) cnt[loc[j]]++;
    int excl[NEXP];
#pragma unroll
    for (int e = 0; e < NEXP; e++) {
        int inc = cnt[e];
#pragma unroll
        for (int off = 1; off < 32; off <<= 1) {
            int n = __shfl_up_sync(0xffffffffu, inc, off);
            if (lane >= off) inc += n;
        }
        excl[e] = inc - cnt[e];
        if (lane == 31) wsum[wid][e] = inc;
    }
    __syncthreads();
    if (tid == 0) {
#pragma unroll
        for (int e = 0; e < NEXP; e++) {
            int run = 0;
            for (int w = 0; w < 8; w++) { wbase[w][e] = run; run += wsum[w][e]; }
            g_cnt[e] = (run < CAP) ? run : CAP;
        }
    }
    __syncthreads();
    int pos[NEXP];
#pragma unroll
    for (int e = 0; e < NEXP; e++) pos[e] = wbase[wid][e] + excl[e];
#pragma unroll
    for (int j = 0; j < 32; j++) {
        int e = loc[j];
        int p = pos[e]++;
        g_slot[tid * 32 + j] = (p < CAP) ? p : -1;
    }
}

// ---------------- 3. dispatch (gather tokens into [E,C,M]) ----------------
__global__ void gather_kernel(const float* __restrict__ x) {
    int t = blockIdx.x;
    int sl = g_slot[t];
    if (sl < 0) return;
    int e = g_idx[t];
    const float4* src = (const float4*)(x + (size_t)t * DMODEL);
    float4* dst = (float4*)(g_disp + ((size_t)e * CAP + sl) * DMODEL);
    dst[threadIdx.x] = src[threadIdx.x];
}

// ---------------- 4. per-expert SGEMM: M-packed accumulators (zero A-MOVs) ----------------
// 128x128 tile, K slab 1024, 256 threads, 16(M)x4(N) microtile, packed f32x2 FMA.
// acc[m][n] = packed pair (C[2m][n], C[2m+1][n]); A pairs come straight from SMEM
// (adjacent M-rows are adjacent floats) -> only B needs duplication (4 pk per kk).
// Warp shape 2 lty x 16 ltx: A-frag 4 LDS.128 @ 1 wavefront each, B-frag 1 LDS.128 @ 2 wf.
// As double-buffered (reg-staged), Bs triple-buffered (cp.async), one barrier per chunk.
template<int N, int LDA, bool RELU, int PHASE>
__global__ __launch_bounds__(256, 2)
void sgemm_kernel(const float* __restrict__ Bw, const float* __restrict__ biasb) {
    __shared__ __align__(16) float As[2][BK][PADW];
    __shared__ __align__(16) float Bs[3][BK][PADW];

    constexpr int KD = 1024;             // K depth per slab
    const int z  = blockIdx.z;
    const int e  = (PHASE == 1) ? z : (z & 7);
    const int ks = (PHASE == 1) ? 0 : (z >> 3);
    const int bm = blockIdx.y * 128;
    if (bm >= g_cnt[e]) return;          // expert under-filled: skip

    const float* A;
    float* Cc;
    if (PHASE == 1) {
        A  = g_disp + (size_t)e * CAP * DMODEL;
        Cc = g_h    + (size_t)e * CAP * DFF;
    } else {
        A  = g_h    + (size_t)e * CAP * DFF + (size_t)ks * KD;
        Cc = g_part + (size_t)z * CAP * DMODEL;
    }
    const float* B    = (PHASE == 1) ? (Bw + (size_t)e * KD * N)
                                     : (Bw + (size_t)e * DFF * N + (size_t)ks * KD * N);
    const float* bias = biasb + (size_t)e * N;

    const int bn = blockIdx.x * 128;
    const int tid = threadIdx.x;
    const int wid = tid >> 5, lane = tid & 31;
    // thread grid 8 (M) x 32 (N): warps 4 wy x 2 wx; lanes 2 lty x 16 ltx
    const int ty = (wid >> 1) * 2 + (lane >> 4);   // 0..7   (16 M rows each)
    const int tx = (wid & 1) * 16 + (lane & 15);   // 0..31  (4 N cols each)
    constexpr int NCH = KD / BK;

    const int ar  = tid >> 1;
    const int ak0 = (tid & 1) * 8;
    const float* Aptr = A + (size_t)(bm + ar) * LDA + ak0;

    const int bk0  = tid >> 4;
    const int bseg = (tid * 2) & 31;
    const float* Bptr = B + (size_t)bk0 * N + bn + bseg * 4;
    u32 bs_st[3] = { smem_u32(&Bs[0][bk0][bseg * 4]),
                     smem_u32(&Bs[1][bk0][bseg * 4]),
                     smem_u32(&Bs[2][bk0][bseg * 4]) };

    // prologue: A(0), A(1) in regs; B(0), B(1) in flight
    float4 areg[2][2];
    areg[0][0] = *(const float4*)(Aptr);
    areg[0][1] = *(const float4*)(Aptr + 4);
    cpa16(bs_st[0],      Bptr);
    cpa16(bs_st[0] + 16, Bptr + 4);
    cpa_commit();
    areg[1][0] = *(const float4*)(Aptr + BK);
    areg[1][1] = *(const float4*)(Aptr + BK + 4);
    cpa16(bs_st[1],      Bptr + (size_t)BK * N);
    cpa16(bs_st[1] + 16, Bptr + (size_t)BK * N + 4);
    cpa_commit();

    ull acc[8][4];   // acc[m][n] = (C[ty*16+2m][tx*4+n], C[ty*16+2m+1][tx*4+n])
#pragma unroll
    for (int i = 0; i < 8; i++)
#pragma unroll
        for (int j = 0; j < 4; j++) acc[i][j] = 0ull;

#pragma unroll 1
    for (int c = 0; c < NCH; c++) {
        const int sa = c & 1;
        // store A chunk c (in regs) transposed into As[sa]; safe pre-barrier
        // (readers of As[sa] finished before the previous barrier).
#pragma unroll
        for (int q = 0; q < 2; q++) {
            float4 v = areg[sa][q];
            int kq = ak0 + q * 4;
            As[sa][kq + 0][ar] = v.x;
            As[sa][kq + 1][ar] = v.y;
            As[sa][kq + 2][ar] = v.z;
            As[sa][kq + 3][ar] = v.w;
        }
        if (c + 1 < NCH) cpa_wait1(); else cpa_wait0();   // B(c) landed
        __syncthreads();                                  // As[sa] + Bs[c%3] visible
        const int sb = c % 3;
#pragma unroll
        for (int kk = 0; kk < BK; kk++) {
            // A: 16 M-values as 8 natural packed pairs (zero MOVs)
            const ull* arow = (const ull*)&As[sa][kk][ty * 16];
            ulonglong2 A0 = *(const ulonglong2*)(arow);
            ulonglong2 A1 = *(const ulonglong2*)(arow + 2);
            ulonglong2 A2 = *(const ulonglong2*)(arow + 4);
            ulonglong2 A3 = *(const ulonglong2*)(arow + 6);
            ull am[8] = { A0.x, A0.y, A1.x, A1.y, A2.x, A2.y, A3.x, A3.y };
            // B: 4 N-values, duplicated (4 pk)
            float4 b = *(const float4*)&Bs[sb][kk][tx * 4];
            ull bp[4] = { pk(b.x, b.x), pk(b.y, b.y), pk(b.z, b.z), pk(b.w, b.w) };
#pragma unroll
            for (int m = 0; m < 8; m++) {
                acc[m][0] = ffma2(am[m], bp[0], acc[m][0]);
                acc[m][1] = ffma2(am[m], bp[1], acc[m][1]);
                acc[m][2] = ffma2(am[m], bp[2], acc[m][2]);
                acc[m][3] = ffma2(am[m], bp[3], acc[m][3]);
            }
        }
        // post-compute: prefetch chunk c+2 (A -> regs, B -> Bs[(c+2)%3]).
        if (c + 2 < NCH) {
            const float* ap2 = Aptr + (size_t)(c + 2) * BK;
            areg[sa][0] = *(const float4*)(ap2);
            areg[sa][1] = *(const float4*)(ap2 + 4);
            const float* bp2g = Bptr + (size_t)(c + 2) * BK * N;
            u32 bss = bs_st[(c + 2) % 3];
            cpa16(bss,      bp2g);
            cpa16(bss + 16, bp2g + 4);
            cpa_commit();
        }
    }

    // epilogue: each thread owns rows bm+ty*16+(0..15), cols bn+tx*4+(0..3)
    float bv[4];
    if (PHASE == 1) {
#pragma unroll
        for (int j = 0; j < 4; j++) bv[j] = bias[bn + tx * 4 + j];
    }
#pragma unroll
    for (int m = 0; m < 8; m++) {
        float lo[4], hi[4];
#pragma unroll
        for (int n = 0; n < 4; n++) upk(acc[m][n], lo[n], hi[n]);
        if (PHASE == 1) {
#pragma unroll
            for (int n = 0; n < 4; n++) {
                lo[n] = fmaxf(lo[n] + bv[n], 0.0f);
                hi[n] = fmaxf(hi[n] + bv[n], 0.0f);
            }
        }
        float* c0 = Cc + (size_t)(bm + ty * 16 + 2 * m) * N + bn + tx * 4;
        *(float4*)c0       = make_float4(lo[0], lo[1], lo[2], lo[3]);
        *(float4*)(c0 + N) = make_float4(hi[0], hi[1], hi[2], hi[3]);
    }
}

// ---------------- 5. combine (+ split-K reduction, fixed order -> deterministic) ----------------
__global__ void combine_kernel(const float* __restrict__ b2, float* __restrict__ out) {
    int t = blockIdx.x;
    int sl = g_slot[t];
    float4* o = (float4*)(out + (size_t)t * DMODEL);
    int i = threadIdx.x;
    if (sl < 0) {
        o[i] = make_float4(0.f, 0.f, 0.f, 0.f);
        return;
    }
    float g = g_gate[t];
    int e = g_idx[t];
    const size_t stride = (size_t)NEXP * CAP * DMODEL;
    const float* p = g_part + ((size_t)e * CAP + sl) * DMODEL + i * 4;
    float4 s = *(const float4*)p;
#pragma unroll
    for (int ks = 1; ks < SPLITK; ks++) {
        float4 v = *(const float4*)(p + ks * stride);
        s.x += v.x; s.y += v.y; s.z += v.z; s.w += v.w;
    }
    float4 b = *(const float4*)(b2 + (size_t)e * DMODEL + i * 4);
    o[i] = make_float4((s.x + b.x) * g, (s.y + b.y) * g,
                       (s.z + b.z) * g, (s.w + b.w) * g);
}

// ---------------- launch ----------------
extern "C" void kernel_launch(void* const* d_in, const int* in_sizes, int n_in,
                              void* d_out, int out_size) {
    const float* x  = (const float*)d_in[0];   // [4,2048,1024]
    const float* wg = (const float*)d_in[1];   // [1024,8]
    const float* w1 = (const float*)d_in[2];   // [8,1024,4096]
    const float* b1 = (const float*)d_in[3];   // [8,4096]
    const float* w2 = (const float*)d_in[4];   // [8,4096,1024]
    const float* b2 = (const float*)d_in[5];   // [8,1024]
    float* out = (float*)d_out;                // [4,2048,1024]

    gate_kernel<<<T_TOK / 8, 256>>>(x, wg);
    scan_kernel<<<1, 256>>>();
    gather_kernel<<<T_TOK, 256>>>(x);
    // GEMM1: full K=1024 per block
    sgemm_kernel<DFF, DMODEL, true, 1>
        <<<dim3(DFF / 128, CAP / 128, NEXP), 256>>>(w1, b1);
    // GEMM2: split-K=4 slabs of 1024 -> partials
    sgemm_kernel<DMODEL, DFF, false, 2>
        <<<dim3(DMODEL / 128, CAP / 128, NEXP * SPLITK), 256>>>(w2, nullptr);
    combine_kernel<<<T_TOK, 256>>>(b2, out);
}

// round 11
// speedup vs baseline: 1.6419x; 1.0064x over previous
#include <cuda_runtime.h>

#define T_TOK   8192
#define DMODEL  1024
#define NEXP    8
#define DFF     4096
#define CAP     1280   // int(1.25 * 8192 / 8)
#define BK      16
#define PADW    160    // 640B row stride = 5 x 128B: every SMEM row sector-aligned
#define SPLITK  4

typedef unsigned int u32;
typedef unsigned long long ull;

// ---------------- scratch (device globals; no allocation) ----------------
__device__ float g_disp[(size_t)NEXP * CAP * DMODEL];              // 40 MB
__device__ float g_h   [(size_t)NEXP * CAP * DFF];                 // 167 MB
__device__ float g_part[(size_t)SPLITK * NEXP * CAP * DMODEL];     // 160 MB
__device__ int   g_idx [T_TOK];
__device__ float g_gate[T_TOK];
__device__ int   g_slot[T_TOK];
__device__ int   g_cnt [NEXP];

// ---------------- packed f32x2 + async-copy helpers ----------------
__device__ __forceinline__ ull pk(float x, float y) {
    ull r; asm("mov.b64 %0, {%1, %2};" : "=l"(r) : "f"(x), "f"(y)); return r;
}
__device__ __forceinline__ void upk(ull v, float& x, float& y) {
    asm("mov.b64 {%0, %1}, %2;" : "=f"(x), "=f"(y) : "l"(v));
}
__device__ __forceinline__ ull ffma2(ull a, ull b, ull c) {
    ull d; asm("fma.rn.f32x2 %0, %1, %2, %3;" : "=l"(d) : "l"(a), "l"(b), "l"(c)); return d;
}
__device__ __forceinline__ u32 smem_u32(const void* p) {
    u32 a; asm("{ .reg .u64 t; cvta.to.shared.u64 t, %1; cvt.u32.u64 %0, t; }" : "=r"(a) : "l"(p));
    return a;
}
__device__ __forceinline__ void cpa16(u32 s, const void* g) {
    asm volatile("cp.async.cg.shared.global [%0], [%1], 16;" :: "r"(s), "l"(g));
}
__device__ __forceinline__ void cpa_commit() { asm volatile("cp.async.commit_group;" ::: "memory"); }
__device__ __forceinline__ void cpa_wait1()  { asm volatile("cp.async.wait_group 1;" ::: "memory"); }
__device__ __forceinline__ void cpa_wait0()  { asm volatile("cp.async.wait_group 0;" ::: "memory"); }

// ---------------- 1. gating ----------------
__global__ void gate_kernel(const float* __restrict__ x, const float* __restrict__ wg) {
    __shared__ float wgT[NEXP][DMODEL];
    int tid = threadIdx.x;
    for (int i = tid; i < DMODEL * NEXP; i += 256)
        wgT[i & 7][i >> 3] = wg[i];
    __syncthreads();
    int warp = tid >> 5, lane = tid & 31;
    int t = blockIdx.x * 8 + warp;
    const float* xr = x + (size_t)t * DMODEL;
    float acc[NEXP];
#pragma unroll
    for (int e = 0; e < NEXP; e++) acc[e] = 0.0f;
    for (int m = lane; m < DMODEL; m += 32) {
        float xv = xr[m];
#pragma unroll
        for (int e = 0; e < NEXP; e++) acc[e] += xv * wgT[e][m];
    }
#pragma unroll
    for (int e = 0; e < NEXP; e++)
#pragma unroll
        for (int o = 16; o; o >>= 1)
            acc[e] += __shfl_xor_sync(0xffffffffu, acc[e], o);
    if (lane == 0) {
        float mx = acc[0]; int a = 0;
#pragma unroll
        for (int e = 1; e < NEXP; e++)
            if (acc[e] > mx) { mx = acc[e]; a = e; }   // first-max, matches jnp.argmax
        float s = 0.0f;
#pragma unroll
        for (int e = 0; e < NEXP; e++) s += expf(acc[e] - mx);
        g_idx[t]  = a;
        g_gate[t] = 1.0f / s;
    }
}

// ---------------- 2. queue positions + per-expert counts ----------------
__global__ void scan_kernel() {
    __shared__ int wsum[8][NEXP];
    __shared__ int wbase[8][NEXP];
    int tid = threadIdx.x, wid = tid >> 5, lane = tid & 31;
    int loc[32];
    const int4* gp = (const int4*)(g_idx + tid * 32);
#pragma unroll
    for (int v = 0; v < 8; v++) {
        int4 q = gp[v];
        loc[v * 4 + 0] = q.x; loc[v * 4 + 1] = q.y;
        loc[v * 4 + 2] = q.z; loc[v * 4 + 3] = q.w;
    }
    int cnt[NEXP];
#pragma unroll
    for (int e = 0; e < NEXP; e++) cnt[e] = 0;
#pragma unroll
    for (int j = 0; j < 32; j++) cnt[loc[j]]++;
    int excl[NEXP];
#pragma unroll
    for (int e = 0; e < NEXP; e++) {
        int inc = cnt[e];
#pragma unroll
        for (int off = 1; off < 32; off <<= 1) {
            int n = __shfl_up_sync(0xffffffffu, inc, off);
            if (lane >= off) inc += n;
        }
        excl[e] = inc - cnt[e];
        if (lane == 31) wsum[wid][e] = inc;
    }
    __syncthreads();
    if (tid == 0) {
#pragma unroll
        for (int e = 0; e < NEXP; e++) {
            int run = 0;
            for (int w = 0; w < 8; w++) { wbase[w][e] = run; run += wsum[w][e]; }
            g_cnt[e] = (run < CAP) ? run : CAP;
        }
    }
    __syncthreads();
    int pos[NEXP];
#pragma unroll
    for (int e = 0; e < NEXP; e++) pos[e] = wbase[wid][e] + excl[e];
#pragma unroll
    for (int j = 0; j < 32; j++) {
        int e = loc[j];
        int p = pos[e]++;
        g_slot[tid * 32 + j] = (p < CAP) ? p : -1;
    }
}

// ---------------- 3. dispatch (gather tokens into [E,C,M]) ----------------
__global__ void gather_kernel(const float* __restrict__ x) {
    int t = blockIdx.x;
    int sl = g_slot[t];
    if (sl < 0) return;
    int e = g_idx[t];
    const float4* src = (const float4*)(x + (size_t)t * DMODEL);
    float4* dst = (float4*)(g_disp + ((size_t)e * CAP + sl) * DMODEL);
    dst[threadIdx.x] = src[threadIdx.x];
}

// ---------------- 4. per-expert SGEMM: M-packed acc + 128B-aligned SMEM rows ----------------
// 128x128 tile, K slab 1024, 256 threads, 16(M)x4(N) microtile, packed f32x2 FMA.
// acc[m][n] = packed pair (C[2m][n], C[2m+1][n]); A pairs straight from SMEM.
// PADW=160 -> 640B rows, 128B-aligned: A-frag = 1 wavefront, B-frag = 2. 6 wf/kk/warp.
// As double-buffered (reg-staged), Bs triple-buffered (cp.async), one barrier per chunk.
template<int N, int LDA, bool RELU, int PHASE>
__global__ __launch_bounds__(256, 2)
void sgemm_kernel(const float* __restrict__ Bw, const float* __restrict__ biasb) {
    __shared__ __align__(128) float As[2][BK][PADW];
    __shared__ __align__(128) float Bs[3][BK][PADW];

    constexpr int KD = 1024;             // K depth per slab
    const int z  = blockIdx.z;
    const int e  = (PHASE == 1) ? z : (z & 7);
    const int ks = (PHASE == 1) ? 0 : (z >> 3);
    const int bm = blockIdx.y * 128;
    if (bm >= g_cnt[e]) return;          // expert under-filled: skip

    const float* A;
    float* Cc;
    if (PHASE == 1) {
        A  = g_disp + (size_t)e * CAP * DMODEL;
        Cc = g_h    + (size_t)e * CAP * DFF;
    } else {
        A  = g_h    + (size_t)e * CAP * DFF + (size_t)ks * KD;
        Cc = g_part + (size_t)z * CAP * DMODEL;
    }
    const float* B    = (PHASE == 1) ? (Bw + (size_t)e * KD * N)
                                     : (Bw + (size_t)e * DFF * N + (size_t)ks * KD * N);
    const float* bias = biasb + (size_t)e * N;

    const int bn = blockIdx.x * 128;
    const int tid = threadIdx.x;
    const int wid = tid >> 5, lane = tid & 31;
    // thread grid 8 (M) x 32 (N): warps 4 wy x 2 wx; lanes 2 lty x 16 ltx
    const int ty = (wid >> 1) * 2 + (lane >> 4);   // 0..7   (16 M rows each)
    const int tx = (wid & 1) * 16 + (lane & 15);   // 0..31  (4 N cols each)
    constexpr int NCH = KD / BK;

    const int ar  = tid >> 1;
    const int ak0 = (tid & 1) * 8;
    const float* Aptr = A + (size_t)(bm + ar) * LDA + ak0;

    const int bk0  = tid >> 4;
    const int bseg = (tid * 2) & 31;
    const float* Bptr = B + (size_t)bk0 * N + bn + bseg * 4;
    u32 bs_st[3] = { smem_u32(&Bs[0][bk0][bseg * 4]),
                     smem_u32(&Bs[1][bk0][bseg * 4]),
                     smem_u32(&Bs[2][bk0][bseg * 4]) };

    // prologue: A(0), A(1) in regs; B(0), B(1) in flight
    float4 areg[2][2];
    areg[0][0] = *(const float4*)(Aptr);
    areg[0][1] = *(const float4*)(Aptr + 4);
    cpa16(bs_st[0],      Bptr);
    cpa16(bs_st[0] + 16, Bptr + 4);
    cpa_commit();
    areg[1][0] = *(const float4*)(Aptr + BK);
    areg[1][1] = *(const float4*)(Aptr + BK + 4);
    cpa16(bs_st[1],      Bptr + (size_t)BK * N);
    cpa16(bs_st[1] + 16, Bptr + (size_t)BK * N + 4);
    cpa_commit();

    ull acc[8][4];   // acc[m][n] = (C[ty*16+2m][tx*4+n], C[ty*16+2m+1][tx*4+n])
#pragma unroll
    for (int i = 0; i < 8; i++)
#pragma unroll
        for (int j = 0; j < 4; j++) acc[i][j] = 0ull;

#pragma unroll 1
    for (int c = 0; c < NCH; c++) {
        const int sa = c & 1;
        // store A chunk c (in regs) transposed into As[sa]; safe pre-barrier
        // (readers of As[sa] finished before the previous barrier).
#pragma unroll
        for (int q = 0; q < 2; q++) {
            float4 v = areg[sa][q];
            int kq = ak0 + q * 4;
            As[sa][kq + 0][ar] = v.x;
            As[sa][kq + 1][ar] = v.y;
            As[sa][kq + 2][ar] = v.z;
            As[sa][kq + 3][ar] = v.w;
        }
        if (c + 1 < NCH) cpa_wait1(); else cpa_wait0();   // B(c) landed
        __syncthreads();                                  // As[sa] + Bs[c%3] visible
        const int sb = c % 3;
#pragma unroll
        for (int kk = 0; kk < BK; kk++) {
            // A: 16 M-values as 8 natural packed pairs (zero MOVs, 1 wf per LDS.128)
            const ull* arow = (const ull*)&As[sa][kk][ty * 16];
            ulonglong2 A0 = *(const ulonglong2*)(arow);
            ulonglong2 A1 = *(const ulonglong2*)(arow + 2);
            ulonglong2 A2 = *(const ulonglong2*)(arow + 4);
            ulonglong2 A3 = *(const ulonglong2*)(arow + 6);
            ull am[8] = { A0.x, A0.y, A1.x, A1.y, A2.x, A2.y, A3.x, A3.y };
            // B: 4 N-values, duplicated (4 pk)
            float4 b = *(const float4*)&Bs[sb][kk][tx * 4];
            ull bp[4] = { pk(b.x, b.x), pk(b.y, b.y), pk(b.z, b.z), pk(b.w, b.w) };
#pragma unroll
            for (int m = 0; m < 8; m++) {
                acc[m][0] = ffma2(am[m], bp[0], acc[m][0]);
                acc[m][1] = ffma2(am[m], bp[1], acc[m][1]);
                acc[m][2] = ffma2(am[m], bp[2], acc[m][2]);
                acc[m][3] = ffma2(am[m], bp[3], acc[m][3]);
            }
        }
        // post-compute: prefetch chunk c+2 (A -> regs, B -> Bs[(c+2)%3]).
        if (c + 2 < NCH) {
            const float* ap2 = Aptr + (size_t)(c + 2) * BK;
            areg[sa][0] = *(const float4*)(ap2);
            areg[sa][1] = *(const float4*)(ap2 + 4);
            const float* bp2g = Bptr + (size_t)(c + 2) * BK * N;
            u32 bss = bs_st[(c + 2) % 3];
            cpa16(bss,      bp2g);
            cpa16(bss + 16, bp2g + 4);
            cpa_commit();
        }
    }

    // epilogue: each thread owns rows bm+ty*16+(0..15), cols bn+tx*4+(0..3)
    float bv[4];
    if (PHASE == 1) {
#pragma unroll
        for (int j = 0; j < 4; j++) bv[j] = bias[bn + tx * 4 + j];
    }
#pragma unroll
    for (int m = 0; m < 8; m++) {
        float lo[4], hi[4];
#pragma unroll
        for (int n = 0; n < 4; n++) upk(acc[m][n], lo[n], hi[n]);
        if (PHASE == 1) {
#pragma unroll
            for (int n = 0; n < 4; n++) {
                lo[n] = fmaxf(lo[n] + bv[n], 0.0f);
                hi[n] = fmaxf(hi[n] + bv[n], 0.0f);
            }
        }
        float* c0 = Cc + (size_t)(bm + ty * 16 + 2 * m) * N + bn + tx * 4;
        *(float4*)c0       = make_float4(lo[0], lo[1], lo[2], lo[3]);
        *(float4*)(c0 + N) = make_float4(hi[0], hi[1], hi[2], hi[3]);
    }
}

// ---------------- 5. combine (+ split-K reduction, fixed order -> deterministic) ----------------
__global__ void combine_kernel(const float* __restrict__ b2, float* __restrict__ out) {
    int t = blockIdx.x;
    int sl = g_slot[t];
    float4* o = (float4*)(out + (size_t)t * DMODEL);
    int i = threadIdx.x;
    if (sl < 0) {
        o[i] = make_float4(0.f, 0.f, 0.f, 0.f);
        return;
    }
    float g = g_gate[t];
    int e = g_idx[t];
    const size_t stride = (size_t)NEXP * CAP * DMODEL;
    const float* p = g_part + ((size_t)e * CAP + sl) * DMODEL + i * 4;
    float4 s = *(const float4*)p;
#pragma unroll
    for (int ks = 1; ks < SPLITK; ks++) {
        float4 v = *(const float4*)(p + ks * stride);
        s.x += v.x; s.y += v.y; s.z += v.z; s.w += v.w;
    }
    float4 b = *(const float4*)(b2 + (size_t)e * DMODEL + i * 4);
    o[i] = make_float4((s.x + b.x) * g, (s.y + b.y) * g,
                       (s.z + b.z) * g, (s.w + b.w) * g);
}

// ---------------- launch ----------------
extern "C" void kernel_launch(void* const* d_in, const int* in_sizes, int n_in,
                              void* d_out, int out_size) {
    const float* x  = (const float*)d_in[0];   // [4,2048,1024]
    const float* wg = (const float*)d_in[1];   // [1024,8]
    const float* w1 = (const float*)d_in[2];   // [8,1024,4096]
    const float* b1 = (const float*)d_in[3];   // [8,4096]
    const float* w2 = (const float*)d_in[4];   // [8,4096,1024]
    const float* b2 = (const float*)d_in[5];   // [8,1024]
    float* out = (float*)d_out;                // [4,2048,1024]

    gate_kernel<<<T_TOK / 8, 256>>>(x, wg);
    scan_kernel<<<1, 256>>>();
    gather_kernel<<<T_TOK, 256>>>(x);
    // GEMM1: full K=1024 per block
    sgemm_kernel<DFF, DMODEL, true, 1>
        <<<dim3(DFF / 128, CAP / 128, NEXP), 256>>>(w1, b1);
    // GEMM2: split-K=4 slabs of 1024 -> partials
    sgemm_kernel<DMODEL, DFF, false, 2>
        <<<dim3(DMODEL / 128, CAP / 128, NEXP * SPLITK), 256>>>(w2, nullptr);
    combine_kernel<<<T_TOK, 256>>>(b2, out);
}